// round 13
// baseline (speedup 1.0000x reference)
#include <cuda_runtime.h>
#include <cuda_fp16.h>
#include <cstdint>

#define B_    32
#define IC    512
#define OC    512
#define WDIM  512

// ---------------------------------------------------------------------------
// Helpers (base-target PTX only: cp.async + mma.sync + ldmatrix)
// ---------------------------------------------------------------------------
__device__ __forceinline__ uint32_t smem_to_u32(const void* p) {
    uint32_t a;
    asm("{ .reg .u64 t; cvta.to.shared.u64 t, %1; cvt.u32.u64 %0, t; }"
        : "=r"(a) : "l"(p));
    return a;
}

__device__ __forceinline__ void cp_async16(uint32_t s, const void* g) {
    asm volatile("cp.async.cg.shared.global [%0], [%1], 16;" :: "r"(s), "l"(g));
}
__device__ __forceinline__ void cp_commit() {
    asm volatile("cp.async.commit_group;");
}
__device__ __forceinline__ void cp_wait0() {
    asm volatile("cp.async.wait_group 0;" ::: "memory");
}

__device__ __forceinline__ void ldsm_x4(uint32_t* r, uint32_t addr) {
    asm volatile("ldmatrix.sync.aligned.m8n8.x4.shared.b16 {%0,%1,%2,%3}, [%4];"
                 : "=r"(r[0]), "=r"(r[1]), "=r"(r[2]), "=r"(r[3]) : "r"(addr));
}

// fp16 MMA m16n8k16, fp32 accumulate
__device__ __forceinline__ void mma_f16(float* d, const uint32_t* a,
                                        const uint32_t b0, const uint32_t b1) {
    asm volatile(
        "mma.sync.aligned.m16n8k16.row.col.f32.f16.f16.f32 "
        "{%0,%1,%2,%3}, {%4,%5,%6,%7}, {%8,%9}, {%0,%1,%2,%3};"
        : "+f"(d[0]), "+f"(d[1]), "+f"(d[2]), "+f"(d[3])
        : "r"(a[0]), "r"(a[1]), "r"(a[2]), "r"(a[3]), "r"(b0), "r"(b1));
}

// ---------------------------------------------------------------------------
// Scratch
// ---------------------------------------------------------------------------
__device__ float  g_style[B_ * IC];                  // style[b,i] (fp32)
__device__ float  g_cs[OC * IC];                     // s_conv^2 * sum_k cw^2
__device__ float  g_f[B_ * OC];                      // demod factor
__device__ __half g_cwrh[9 * OC * IC];               // [s][o][i]  fp16
__device__ __half g_xsph[(size_t)B_ * 66 * 66 * IC]; // [b][h][w][i] fp16, padded

// ---------------------------------------------------------------------------
// prep1: border zeroing + cwr relayout + cs reduction (fused)
// ---------------------------------------------------------------------------
#define BORDER_BLKS 16640
#define CWR_BLKS    9216
#define CS_BLKS     1024

__global__ void prep1_kernel(const float* __restrict__ cw) {
    const int bid = blockIdx.x;
    if (bid < BORDER_BLKS) {
        const int idx = bid * 256 + threadIdx.x;      // 32*260*512
        const int i = idx & 511;
        const int p = idx >> 9;
        const int b = p / 260;
        const int r = p - b * 260;
        int h, w;
        if (r < 66)       { h = 0;  w = r; }
        else if (r < 132) { h = 65; w = r - 66; }
        else { int r2 = r - 132; h = 1 + (r2 >> 1); w = (r2 & 1) * 65; }
        g_xsph[((size_t)(b * 66 + h) * 66 + w) * IC + i] = __half(0.f);
    } else if (bid < BORDER_BLKS + CWR_BLKS) {
        const int j = (bid - BORDER_BLKS) * 256 + threadIdx.x;  // 9*512*512
        const int s = j >> 18;
        const int rem = j & 262143;
        const int o = rem >> 9, i = rem & 511;
        g_cwrh[j] = __float2half_rn(cw[(size_t)(o * IC + i) * 9 + s]);
    } else {
        const int idx = (bid - BORDER_BLKS - CWR_BLKS) * 256 + threadIdx.x;
        const float* p = cw + (size_t)idx * 9;
        float s = 0.f;
#pragma unroll
        for (int k = 0; k < 9; k++) { float v = p[k]; s += v * v; }
        g_cs[idx] = s * (1.0f / 2304.0f);
    }
}

// ---------------------------------------------------------------------------
// style[b,i] = (w[b,:] . lin_w[i,:]) / 16 + lin_b[i]   (one warp per (b,i))
// ---------------------------------------------------------------------------
__global__ void style_kernel(const float* __restrict__ w,
                             const float* __restrict__ lin_w,
                             const float* __restrict__ lin_b) {
    const int gw  = (blockIdx.x * 256 + threadIdx.x) >> 5;
    const int lid = threadIdx.x & 31;
    const int b = gw >> 9, i = gw & 511;
    const float* wr = w + b * WDIM;
    const float* lw = lin_w + (size_t)i * WDIM;
    float acc = 0.f;
#pragma unroll
    for (int d = 0; d < WDIM / 32; d++)
        acc += wr[d * 32 + lid] * lw[d * 32 + lid];
#pragma unroll
    for (int off = 16; off > 0; off >>= 1)
        acc += __shfl_xor_sync(0xffffffffu, acc, off);
    if (lid == 0) g_style[b * IC + i] = acc * 0.0625f + lin_b[i];
}

// ---------------------------------------------------------------------------
// prep3: xsp transpose+premultiply (blocks [0,2048)) + f demod ([2048,4096))
// ---------------------------------------------------------------------------
__global__ void prep3_kernel(const float* __restrict__ x) {
    if (blockIdx.x < 2048) {
        __shared__ float sm[64][65];
        const int bh = blockIdx.x;
        const int b = bh >> 6, h = bh & 63;
        const int tx = threadIdx.x & 63, ty = threadIdx.x >> 6;
        for (int ic = 0; ic < 8; ic++) {
#pragma unroll
            for (int r = 0; r < 16; r++) {
                const int il = ty + r * 4;
                const int i = ic * 64 + il;
                sm[il][tx] = x[((size_t)(b * IC) + i) * 4096 + h * 64 + tx] *
                             g_style[b * IC + i];
            }
            __syncthreads();
#pragma unroll
            for (int r = 0; r < 16; r++) {
                const int w = ty + r * 4;
                g_xsph[((size_t)(b * 66 + h + 1) * 66 + (w + 1)) * IC + ic * 64 + tx] =
                    __float2half_rn(sm[tx][w]);
            }
            __syncthreads();
        }
    } else {
        const int gw  = ((blockIdx.x - 2048) * 256 + threadIdx.x) >> 5;
        const int lid = threadIdx.x & 31;
        const int b = gw >> 9, o = gw & 511;
        const float* st = g_style + b * IC;
        const float* cs = g_cs + (size_t)o * IC;
        float acc = 0.f;
#pragma unroll
        for (int d = 0; d < IC / 32; d++) {
            float sv = st[d * 32 + lid];
            acc += sv * sv * cs[d * 32 + lid];
        }
#pragma unroll
        for (int off = 16; off > 0; off >>= 1)
            acc += __shfl_xor_sync(0xffffffffu, acc, off);
        if (lid == 0) g_f[b * OC + o] = (1.0f / 48.0f) * rsqrtf(acc + 1e-8f);
    }
}

// ---------------------------------------------------------------------------
// Main GEMM: fp16 mma.sync m16n8k16, CTA 128x256xBK64, warp tile 64x64,
// 2-stage cp.async double buffer (48 KB/stage, 96 KB total -> occ 2).
// SMEM rows 128B (64 halfs), 8x16B chunks, chunk^(row&7) XOR swizzle.
// 72 k-chunks = 9 shifts x 8 channel-chunks of 64.
// Pipeline per iter: wait0 ; sync ; issue(c+1)->buf^1 ; compute(c, buf).
// ---------------------------------------------------------------------------
#define A_BYTES 16384              // 128*64*2
#define B_BYTES 32768              // 256*64*2
#define STAGE_BYTES (A_BYTES + B_BYTES)   // 48 KB
#define GEMM_SMEM (2 * STAGE_BYTES)       // 96 KB

__global__ void __launch_bounds__(256, 2)
conv_mma_kernel(const float* __restrict__ bias, const float* __restrict__ noise_w,
                const float* __restrict__ noise, float* __restrict__ out) {
    extern __shared__ char smc[];
    const uint32_t sb = smem_to_u32(smc);

    const int t   = threadIdx.x;
    const int wid = t >> 5, lid = t & 31;
    const int m0  = blockIdx.x * 128;    // 4 m-blocks fastest -> L2 B-sharing
    const int nt  = blockIdx.y;          // 0..511
    const int b   = nt >> 4;
    const int h0  = (nt & 15) * 4;       // 4 output rows per tile
    const int hw0 = (nt & 15) * 256;

    const int wm = wid >> 2, wn = wid & 3;
    const int mBase = wm * 64, nBase = wn * 64;
    const int r = lid >> 2, cq = lid & 3;

    // ldmatrix addressing (m16n8k16 canonical fragment maps)
    const int rowin = lid & 7;
    const int jm = lid >> 3;                         // 0..3
    // A x4: jm&1 -> row half, jm>>1 -> k half; 4 m-frags
    uint32_t aRowB[4], aXor[4];
    {
        const int ar = mBase + ((jm & 1) << 3) + rowin;
#pragma unroll
        for (int mi = 0; mi < 4; mi++) {
            aRowB[mi] = (uint32_t)(ar + mi * 16) * 128u;
            aXor[mi]  = (uint32_t)((ar + mi * 16) & 7);
        }
    }
    const uint32_t aCh = (uint32_t)(jm >> 1);        // k-half select
    // B x4: jm&1 -> k half, jm>>1 -> n half; covers 2 n-frags per x4, 4 x4 = n64
    uint32_t bRowB[4], bXor[4];
    {
        const int br = nBase + ((jm >> 1) << 3) + rowin;
#pragma unroll
        for (int np = 0; np < 4; np++) {
            bRowB[np] = (uint32_t)(br + np * 16) * 128u;
            bXor[np]  = (uint32_t)((br + np * 16) & 7);
        }
    }
    const uint32_t bCh = (uint32_t)(jm & 1);         // k-half select

    // loader indices: rows t>>3 (+32 per iter), chunk t&7
    const int lrow0 = t >> 3;
    const int lchk  = t & 7;

    float acc[4][8][4];
#pragma unroll
    for (int a = 0; a < 4; a++)
#pragma unroll
        for (int bq2 = 0; bq2 < 8; bq2++)
#pragma unroll
            for (int cc = 0; cc < 4; cc++) acc[a][bq2][cc] = 0.f;

#define LOAD_STAGE(c_, stg_)                                                    \
    do {                                                                        \
        const int s_  = (c_) >> 3;                                              \
        const int kc_ = (c_) & 7;                                               \
        const int kh_ = s_ / 3, kw_ = s_ - kh_ * 3;                             \
        const uint32_t aBase = sb + (stg_) * STAGE_BYTES;                       \
        const uint32_t bBase = aBase + A_BYTES;                                 \
        const __half* Ag = g_cwrh + ((size_t)(s_ * OC + m0) * IC) + kc_ * 64 +  \
                           lchk * 8;                                            \
        _Pragma("unroll")                                                       \
        for (int it = 0; it < 4; it++) {                                        \
            const int row = lrow0 + it * 32;                                    \
            const uint32_t dst = aBase + row * 128 +                            \
                                 ((lchk ^ (row & 7)) << 4);                     \
            cp_async16(dst, Ag + (size_t)row * IC);                             \
        }                                                                       \
        _Pragma("unroll")                                                       \
        for (int it = 0; it < 8; it++) {                                        \
            const int row = lrow0 + it * 32;                                    \
            const int hg = h0 + (row >> 6) + kh_;                               \
            const int wg = (row & 63) + kw_;                                    \
            const __half* Bg = g_xsph +                                         \
                ((size_t)((b * 66 + hg) * 66 + wg)) * IC + kc_ * 64 + lchk * 8; \
            const uint32_t dst = bBase + row * 128 +                            \
                                 ((lchk ^ (row & 7)) << 4);                     \
            cp_async16(dst, Bg);                                                \
        }                                                                       \
        cp_commit();                                                            \
    } while (0)

    LOAD_STAGE(0, 0);

    int stg = 0;
    for (int c = 0; c < 72; c++) {
        cp_wait0();
        __syncthreads();
        if (c + 1 < 72) LOAD_STAGE(c + 1, stg ^ 1);

        const uint32_t aBaseS = sb + stg * STAGE_BYTES;
        const uint32_t bBaseS = aBaseS + A_BYTES;
#pragma unroll
        for (int ks = 0; ks < 4; ks++) {
            const uint32_t kA = (uint32_t)(ks << 1) + aCh;
            const uint32_t kB = (uint32_t)(ks << 1) + bCh;
            uint32_t af[4][4], bq[4][4];
#pragma unroll
            for (int mi = 0; mi < 4; mi++)
                ldsm_x4(af[mi], aBaseS + aRowB[mi] + ((kA ^ aXor[mi]) << 4));
#pragma unroll
            for (int np = 0; np < 4; np++)
                ldsm_x4(bq[np], bBaseS + bRowB[np] + ((kB ^ bXor[np]) << 4));
#pragma unroll
            for (int mi = 0; mi < 4; mi++)
#pragma unroll
                for (int ni = 0; ni < 8; ni++)
                    mma_f16(acc[mi][ni], af[mi],
                            bq[ni >> 1][(ni & 1) * 2], bq[ni >> 1][(ni & 1) * 2 + 1]);
        }
        stg ^= 1;
    }
#undef LOAD_STAGE

    // Epilogue: out = f[b,o]*acc + bias[o] + noise_w[o]*noise
#pragma unroll
    for (int mi = 0; mi < 4; mi++) {
#pragma unroll
        for (int half = 0; half < 2; half++) {
            const int o = m0 + mBase + mi * 16 + r + half * 8;
            const float fo = g_f[b * OC + o];
            const float bo = bias[o];
            const float nw = noise_w[o];
            const size_t base = ((size_t)b * OC + o) * 4096 + hw0 + nBase;
#pragma unroll
            for (int ni = 0; ni < 8; ni++) {
                const size_t off = base + ni * 8 + cq * 2;
                float2 nv = *reinterpret_cast<const float2*>(noise + off);
                const float d0 = acc[mi][ni][half * 2 + 0];
                const float d1 = acc[mi][ni][half * 2 + 1];
                float2 ov;
                ov.x = fmaf(fo, d0, fmaf(nw, nv.x, bo));
                ov.y = fmaf(fo, d1, fmaf(nw, nv.y, bo));
                *reinterpret_cast<float2*>(out + off) = ov;
            }
        }
    }
}

// ---------------------------------------------------------------------------
extern "C" void kernel_launch(void* const* d_in, const int* in_sizes, int n_in,
                              void* d_out, int out_size) {
    const float* x       = (const float*)d_in[0];
    const float* w       = (const float*)d_in[1];
    const float* conv_w  = (const float*)d_in[2];
    const float* lin_w   = (const float*)d_in[3];
    const float* lin_b   = (const float*)d_in[4];
    const float* bias    = (const float*)d_in[5];
    const float* noise_w = (const float*)d_in[6];
    const float* noise   = (const float*)d_in[7];
    float* out = (float*)d_out;

    prep1_kernel<<<BORDER_BLKS + CWR_BLKS + CS_BLKS, 256>>>(conv_w);
    style_kernel<<<(B_ * IC) / 8, 256>>>(w, lin_w, lin_b);
    prep3_kernel<<<4096, 256>>>(x);

    cudaFuncSetAttribute(conv_mma_kernel,
                         cudaFuncAttributeMaxDynamicSharedMemorySize, GEMM_SMEM);
    conv_mma_kernel<<<dim3(4, 512), 256, GEMM_SMEM>>>(bias, noise_w, noise, out);
}

// round 14
// speedup vs baseline: 3.0637x; 3.0637x over previous
#include <cuda_runtime.h>
#include <cuda_fp16.h>
#include <cstdint>

#define B_    32
#define IC    512
#define OC    512
#define WDIM  512

// ---------------------------------------------------------------------------
// Helpers (base-target PTX only: cp.async + mma.sync + ldmatrix)
// ---------------------------------------------------------------------------
__device__ __forceinline__ uint32_t smem_to_u32(const void* p) {
    uint32_t a;
    asm("{ .reg .u64 t; cvta.to.shared.u64 t, %1; cvt.u32.u64 %0, t; }"
        : "=r"(a) : "l"(p));
    return a;
}

__device__ __forceinline__ void cp_async16(uint32_t s, const void* g) {
    asm volatile("cp.async.cg.shared.global [%0], [%1], 16;" :: "r"(s), "l"(g));
}
__device__ __forceinline__ void cp_commit() {
    asm volatile("cp.async.commit_group;");
}
__device__ __forceinline__ void cp_wait1() {
    asm volatile("cp.async.wait_group 1;" ::: "memory");
}
__device__ __forceinline__ void cp_wait0() {
    asm volatile("cp.async.wait_group 0;" ::: "memory");
}

__device__ __forceinline__ void ldsm_x4(uint32_t* r, uint32_t addr) {
    asm volatile("ldmatrix.sync.aligned.m8n8.x4.shared.b16 {%0,%1,%2,%3}, [%4];"
                 : "=r"(r[0]), "=r"(r[1]), "=r"(r[2]), "=r"(r[3]) : "r"(addr));
}

// fp16 MMA m16n8k16, fp32 accumulate
__device__ __forceinline__ void mma_f16(float* d, const uint32_t* a,
                                        const uint32_t b0, const uint32_t b1) {
    asm volatile(
        "mma.sync.aligned.m16n8k16.row.col.f32.f16.f16.f32 "
        "{%0,%1,%2,%3}, {%4,%5,%6,%7}, {%8,%9}, {%0,%1,%2,%3};"
        : "+f"(d[0]), "+f"(d[1]), "+f"(d[2]), "+f"(d[3])
        : "r"(a[0]), "r"(a[1]), "r"(a[2]), "r"(a[3]), "r"(b0), "r"(b1));
}

// ---------------------------------------------------------------------------
// Scratch
// ---------------------------------------------------------------------------
__device__ float  g_style[B_ * IC];                  // style[b,i] (fp32)
__device__ float  g_cs[OC * IC];                     // s_conv^2 * sum_k cw^2
__device__ float  g_f[B_ * OC];                      // demod factor
__device__ __half g_cwrh[9 * OC * IC];               // [s][o][i]  fp16
__device__ __half g_xsph[(size_t)B_ * 66 * 66 * IC]; // [b][h][w][i] fp16, padded

// ---------------------------------------------------------------------------
// prep1: border zeroing + cwr relayout + cs reduction (fused)
// ---------------------------------------------------------------------------
#define BORDER_BLKS 16640
#define CWR_BLKS    9216
#define CS_BLKS     1024

__global__ void prep1_kernel(const float* __restrict__ cw) {
    const int bid = blockIdx.x;
    if (bid < BORDER_BLKS) {
        const int idx = bid * 256 + threadIdx.x;      // 32*260*512
        const int i = idx & 511;
        const int p = idx >> 9;
        const int b = p / 260;
        const int r = p - b * 260;
        int h, w;
        if (r < 66)       { h = 0;  w = r; }
        else if (r < 132) { h = 65; w = r - 66; }
        else { int r2 = r - 132; h = 1 + (r2 >> 1); w = (r2 & 1) * 65; }
        g_xsph[((size_t)(b * 66 + h) * 66 + w) * IC + i] = __half(0.f);
    } else if (bid < BORDER_BLKS + CWR_BLKS) {
        const int j = (bid - BORDER_BLKS) * 256 + threadIdx.x;  // 9*512*512
        const int s = j >> 18;
        const int rem = j & 262143;
        const int o = rem >> 9, i = rem & 511;
        g_cwrh[j] = __float2half_rn(cw[(size_t)(o * IC + i) * 9 + s]);
    } else {
        const int idx = (bid - BORDER_BLKS - CWR_BLKS) * 256 + threadIdx.x;
        const float* p = cw + (size_t)idx * 9;
        float s = 0.f;
#pragma unroll
        for (int k = 0; k < 9; k++) { float v = p[k]; s += v * v; }
        g_cs[idx] = s * (1.0f / 2304.0f);
    }
}

// ---------------------------------------------------------------------------
// style[b,i] = (w[b,:] . lin_w[i,:]) / 16 + lin_b[i]   (one warp per (b,i))
// ---------------------------------------------------------------------------
__global__ void style_kernel(const float* __restrict__ w,
                             const float* __restrict__ lin_w,
                             const float* __restrict__ lin_b) {
    const int gw  = (blockIdx.x * 256 + threadIdx.x) >> 5;
    const int lid = threadIdx.x & 31;
    const int b = gw >> 9, i = gw & 511;
    const float* wr = w + b * WDIM;
    const float* lw = lin_w + (size_t)i * WDIM;
    float acc = 0.f;
#pragma unroll
    for (int d = 0; d < WDIM / 32; d++)
        acc += wr[d * 32 + lid] * lw[d * 32 + lid];
#pragma unroll
    for (int off = 16; off > 0; off >>= 1)
        acc += __shfl_xor_sync(0xffffffffu, acc, off);
    if (lid == 0) g_style[b * IC + i] = acc * 0.0625f + lin_b[i];
}

// ---------------------------------------------------------------------------
// prep3: xsp transpose+premultiply (blocks [0,2048)) + f demod ([2048,4096))
// ---------------------------------------------------------------------------
__global__ void prep3_kernel(const float* __restrict__ x) {
    if (blockIdx.x < 2048) {
        __shared__ float sm[64][65];
        const int bh = blockIdx.x;
        const int b = bh >> 6, h = bh & 63;
        const int tx = threadIdx.x & 63, ty = threadIdx.x >> 6;
        for (int ic = 0; ic < 8; ic++) {
#pragma unroll
            for (int r = 0; r < 16; r++) {
                const int il = ty + r * 4;
                const int i = ic * 64 + il;
                sm[il][tx] = x[((size_t)(b * IC) + i) * 4096 + h * 64 + tx] *
                             g_style[b * IC + i];
            }
            __syncthreads();
#pragma unroll
            for (int r = 0; r < 16; r++) {
                const int w = ty + r * 4;
                g_xsph[((size_t)(b * 66 + h + 1) * 66 + (w + 1)) * IC + ic * 64 + tx] =
                    __float2half_rn(sm[tx][w]);
            }
            __syncthreads();
        }
    } else {
        const int gw  = ((blockIdx.x - 2048) * 256 + threadIdx.x) >> 5;
        const int lid = threadIdx.x & 31;
        const int b = gw >> 9, o = gw & 511;
        const float* st = g_style + b * IC;
        const float* cs = g_cs + (size_t)o * IC;
        float acc = 0.f;
#pragma unroll
        for (int d = 0; d < IC / 32; d++) {
            float sv = st[d * 32 + lid];
            acc += sv * sv * cs[d * 32 + lid];
        }
#pragma unroll
        for (int off = 16; off > 0; off >>= 1)
            acc += __shfl_xor_sync(0xffffffffu, acc, off);
        if (lid == 0) g_f[b * OC + o] = (1.0f / 48.0f) * rsqrtf(acc + 1e-8f);
    }
}

// ---------------------------------------------------------------------------
// Main GEMM: fp16 mma.sync m16n8k16, CTA 128x128xBK64, 4 warps (2Mx2N),
// warp tile 64x64, 3-stage cp.async ring (32 KB/stage, 96 KB -> occ 2).
// __launch_bounds__(128,2) -> 255-reg cap: 64x64 warp tile fits WITHOUT spill.
// SMEM rows 128B (64 halfs), 8x16B chunks, chunk^(row&7) XOR swizzle.
// 72 k-chunks = 9 shifts x 8 channel-chunks of 64.
// Pipeline per iter: wait(<=1) ; sync ; issue(c+2)->(stg+2)%3 ; compute(stg).
// ---------------------------------------------------------------------------
#define A_BYTES 16384              // 128*64*2
#define STAGE_BYTES 32768          // A 16KB + B 16KB
#define STAGES 3
#define GEMM_SMEM (STAGES * STAGE_BYTES)   // 96 KB

__global__ void __launch_bounds__(128, 2)
conv_mma_kernel(const float* __restrict__ bias, const float* __restrict__ noise_w,
                const float* __restrict__ noise, float* __restrict__ out) {
    extern __shared__ char smc[];
    const uint32_t sb = smem_to_u32(smc);

    const int t   = threadIdx.x;
    const int wid = t >> 5, lid = t & 31;
    const int m0  = blockIdx.x * 128;    // 4 m-blocks fastest -> L2 B-sharing
    const int nt  = blockIdx.y;          // 0..1023
    const int b   = nt >> 5;
    const int h0  = (nt & 31) * 2;       // 2 output rows per tile
    const int hw0 = (nt & 31) * 128;

    const int wm = wid >> 1, wn = wid & 1;
    const int mBase = wm * 64, nBase = wn * 64;
    const int r = lid >> 2, cq = lid & 3;

    // ldmatrix addressing (m16n8k16 canonical fragment maps)
    const int rowin = lid & 7;
    const int jm = lid >> 3;                         // 0..3
    // A x4: jm&1 -> row half, jm>>1 -> k half; 4 m-frags over 64 rows
    uint32_t aRowB[4], aXor[4];
    {
        const int ar = mBase + ((jm & 1) << 3) + rowin;
#pragma unroll
        for (int mi = 0; mi < 4; mi++) {
            aRowB[mi] = (uint32_t)(ar + mi * 16) * 128u;
            aXor[mi]  = (uint32_t)((ar + mi * 16) & 7);
        }
    }
    const uint32_t aCh = (uint32_t)(jm >> 1);        // k-half select
    // B x4: jm&1 -> k half, jm>>1 -> n half; 4 x4 cover n64
    uint32_t bRowB[4], bXor[4];
    {
        const int br = nBase + ((jm >> 1) << 3) + rowin;
#pragma unroll
        for (int np = 0; np < 4; np++) {
            bRowB[np] = (uint32_t)(br + np * 16) * 128u;
            bXor[np]  = (uint32_t)((br + np * 16) & 7);
        }
    }
    const uint32_t bCh = (uint32_t)(jm & 1);         // k-half select

    // loader indices: 128 threads -> rows t>>3 (+16 x8), chunk t&7
    const int lrow0 = t >> 3;            // 0..15
    const int lchk  = t & 7;

    float acc[4][8][4];
#pragma unroll
    for (int a = 0; a < 4; a++)
#pragma unroll
        for (int bq2 = 0; bq2 < 8; bq2++)
#pragma unroll
            for (int cc = 0; cc < 4; cc++) acc[a][bq2][cc] = 0.f;

#define LOAD_STAGE(c_, stg_)                                                    \
    do {                                                                        \
        const int s_  = (c_) >> 3;                                              \
        const int kc_ = (c_) & 7;                                               \
        const int kh_ = s_ / 3, kw_ = s_ - kh_ * 3;                             \
        const uint32_t aBase = sb + (stg_) * STAGE_BYTES;                       \
        const uint32_t bBase = aBase + A_BYTES;                                 \
        const __half* Ag = g_cwrh + ((size_t)(s_ * OC + m0) * IC) + kc_ * 64 +  \
                           lchk * 8;                                            \
        _Pragma("unroll")                                                       \
        for (int it = 0; it < 8; it++) {                                        \
            const int row = lrow0 + it * 16;                                    \
            const uint32_t dst = aBase + row * 128 +                            \
                                 ((lchk ^ (row & 7)) << 4);                     \
            cp_async16(dst, Ag + (size_t)row * IC);                             \
        }                                                                       \
        _Pragma("unroll")                                                       \
        for (int it = 0; it < 8; it++) {                                        \
            const int row = lrow0 + it * 16;                                    \
            const int hg = h0 + (row >> 6) + kh_;                               \
            const int wg = (row & 63) + kw_;                                    \
            const __half* Bg = g_xsph +                                         \
                ((size_t)((b * 66 + hg) * 66 + wg)) * IC + kc_ * 64 + lchk * 8; \
            const uint32_t dst = bBase + row * 128 +                            \
                                 ((lchk ^ (row & 7)) << 4);                     \
            cp_async16(dst, Bg);                                                \
        }                                                                       \
        cp_commit();                                                            \
    } while (0)

    LOAD_STAGE(0, 0);
    LOAD_STAGE(1, 1);

    int stg = 0;
    for (int c = 0; c < 72; c++) {
        if (c < 71) cp_wait1(); else cp_wait0();
        __syncthreads();
        if (c + 2 < 72) {
            const int stg2 = (stg + 2 >= STAGES) ? (stg + 2 - STAGES) : (stg + 2);
            LOAD_STAGE(c + 2, stg2);
        }

        const uint32_t aBaseS = sb + stg * STAGE_BYTES;
        const uint32_t bBaseS = aBaseS + A_BYTES;
#pragma unroll
        for (int ks = 0; ks < 4; ks++) {
            const uint32_t kA = (uint32_t)(ks << 1) + aCh;
            const uint32_t kB = (uint32_t)(ks << 1) + bCh;
            uint32_t af[4][4], bq[4][4];
#pragma unroll
            for (int mi = 0; mi < 4; mi++)
                ldsm_x4(af[mi], aBaseS + aRowB[mi] + ((kA ^ aXor[mi]) << 4));
#pragma unroll
            for (int np = 0; np < 4; np++)
                ldsm_x4(bq[np], bBaseS + bRowB[np] + ((kB ^ bXor[np]) << 4));
#pragma unroll
            for (int mi = 0; mi < 4; mi++)
#pragma unroll
                for (int ni = 0; ni < 8; ni++)
                    mma_f16(acc[mi][ni], af[mi],
                            bq[ni >> 1][(ni & 1) * 2], bq[ni >> 1][(ni & 1) * 2 + 1]);
        }
        stg = (stg + 1 >= STAGES) ? 0 : (stg + 1);
    }
#undef LOAD_STAGE

    // Epilogue: out = f[b,o]*acc + bias[o] + noise_w[o]*noise
#pragma unroll
    for (int mi = 0; mi < 4; mi++) {
#pragma unroll
        for (int half = 0; half < 2; half++) {
            const int o = m0 + mBase + mi * 16 + r + half * 8;
            const float fo = g_f[b * OC + o];
            const float bo = bias[o];
            const float nw = noise_w[o];
            const size_t base = ((size_t)b * OC + o) * 4096 + hw0 + nBase;
#pragma unroll
            for (int ni = 0; ni < 8; ni++) {
                const size_t off = base + ni * 8 + cq * 2;
                float2 nv = *reinterpret_cast<const float2*>(noise + off);
                const float d0 = acc[mi][ni][half * 2 + 0];
                const float d1 = acc[mi][ni][half * 2 + 1];
                float2 ov;
                ov.x = fmaf(fo, d0, fmaf(nw, nv.x, bo));
                ov.y = fmaf(fo, d1, fmaf(nw, nv.y, bo));
                *reinterpret_cast<float2*>(out + off) = ov;
            }
        }
    }
}

// ---------------------------------------------------------------------------
extern "C" void kernel_launch(void* const* d_in, const int* in_sizes, int n_in,
                              void* d_out, int out_size) {
    const float* x       = (const float*)d_in[0];
    const float* w       = (const float*)d_in[1];
    const float* conv_w  = (const float*)d_in[2];
    const float* lin_w   = (const float*)d_in[3];
    const float* lin_b   = (const float*)d_in[4];
    const float* bias    = (const float*)d_in[5];
    const float* noise_w = (const float*)d_in[6];
    const float* noise   = (const float*)d_in[7];
    float* out = (float*)d_out;

    prep1_kernel<<<BORDER_BLKS + CWR_BLKS + CS_BLKS, 256>>>(conv_w);
    style_kernel<<<(B_ * IC) / 8, 256>>>(w, lin_w, lin_b);
    prep3_kernel<<<4096, 256>>>(x);

    cudaFuncSetAttribute(conv_mma_kernel,
                         cudaFuncAttributeMaxDynamicSharedMemorySize, GEMM_SMEM);
    conv_mma_kernel<<<dim3(4, 1024), 128, GEMM_SMEM>>>(bias, noise_w, noise, out);
}